// round 9
// baseline (speedup 1.0000x reference)
#include <cuda_runtime.h>
#include <cuda_fp16.h>

typedef unsigned long long u64;

#define Nn   200000
#define Ee   3200000
#define Bb   512
#define EMB  32
#define HID  64
#define TILE 1024
#define NT   ((Nn + TILE - 1) / TILE)   // 196 scan tiles

// ---------------- scratch (device globals; zero-initialized at module load) ----------
// Invariant: g_deg, g_tilest, g_ticket, g_hg, g_cnt are ZERO at entry of every call
// (module-load init for call 1; k_final_zero restores them at the end of each call).
__device__ uint4 g_h0h [Nn * 4];          // 12.8 MB fp16 h0
__device__ uint4 g_ag1h[Nn * 4];          // 12.8 MB fp16 agg1
__device__ uint4 g_h1h [Nn * 8];          // 25.6 MB fp16 h1
__device__ uint4 g_ag2h[Nn * 8];          // 25.6 MB fp16 agg2
__device__ int   g_csr [Ee];              // 12.8 MB
__device__ int   g_rank[Ee];              // 12.8 MB edge rank within dst
__device__ int   g_rowptr[Nn];
__device__ int   g_deg [Nn];
__device__ float g_dinv[Nn];
__device__ float g_hg  [Bb * HID];
__device__ float g_cnt [Bb];
__device__ volatile unsigned g_tilest[NT];
__device__ int   g_ticket;

// ---------------- helpers ----------------
__device__ __forceinline__ void red4(float4* p, float4 v) {
    asm volatile("red.global.add.v4.f32 [%0], {%1,%2,%3,%4};"
                 :: "l"(p), "f"(v.x), "f"(v.y), "f"(v.z), "f"(v.w) : "memory");
}
__device__ __forceinline__ u64 pack2(float x, float y) {
    u64 r; asm("mov.b64 %0, {%1, %2};" : "=l"(r) : "f"(x), "f"(y)); return r;
}
__device__ __forceinline__ void fma2(u64& d, u64 a, u64 b) {
    asm("fma.rn.f32x2 %0, %1, %2, %0;" : "+l"(d) : "l"(a), "l"(b));
}
__device__ __forceinline__ void unpack2(float& x, float& y, u64 v) {
    asm("mov.b64 {%0, %1}, %2;" : "=f"(x), "=f"(y) : "l"(v));
}
__device__ __forceinline__ unsigned ph2(float a, float b) {
    __half2 h = __floats2half2_rn(a, b); return *(unsigned*)&h;
}
__device__ __forceinline__ float hget(const uint4& q, int ch) {
    unsigned w = (ch < 2) ? q.x : (ch < 4) ? q.y : (ch < 6) ? q.z : q.w;
    __half2 h = *(__half2*)&w;
    return (ch & 1) ? __high2float(h) : __low2float(h);
}
#define ACCM(q, m) { \
    float2 f0 = __half22float2(*(__half2*)&(q).x); \
    float2 f1 = __half22float2(*(__half2*)&(q).y); \
    float2 f2 = __half22float2(*(__half2*)&(q).z); \
    float2 f3 = __half22float2(*(__half2*)&(q).w); \
    a0 = fmaf(m, f0.x, a0); a1 = fmaf(m, f0.y, a1); \
    a2 = fmaf(m, f1.x, a2); a3 = fmaf(m, f1.y, a3); \
    a4 = fmaf(m, f2.x, a4); a5 = fmaf(m, f2.y, a5); \
    a6 = fmaf(m, f3.x, a6); a7 = fmaf(m, f3.y, a7); }

// ---------------- setup kernels ----------------

// degree histogram (atomic return = edge rank) + graph-size histogram
// (g_deg and g_cnt are guaranteed zero at entry)
__global__ void k_deg(const int* __restrict__ dst,
                      const int* __restrict__ graph_ids) {
    int i = blockIdx.x * blockDim.x + threadIdx.x;
    if (i < Ee) g_rank[i] = atomicAdd(&g_deg[dst[i]], 1);
    if (i < Nn) atomicAdd(&g_cnt[graph_ids[i]], 1.0f);
}

// single-pass decoupled-lookback exclusive scan (g_tilest/g_ticket zero at entry)
__global__ void __launch_bounds__(256) k_scan() {
    __shared__ int s_ticket, s_run;
    __shared__ int ssum[256];
    int tid = threadIdx.x;
    if (tid == 0) s_ticket = atomicAdd(&g_ticket, 1);
    __syncthreads();
    int t = s_ticket;
    int base = t * TILE + tid * 4;
    int d[4]; int s = 0;
    #pragma unroll
    for (int it = 0; it < 4; it++) {
        int idx = base + it;
        d[it] = (idx < Nn) ? g_deg[idx] : 0;
        s += d[it];
    }
    ssum[tid] = s; __syncthreads();
    #pragma unroll
    for (int off = 1; off < 256; off <<= 1) {
        int x = (tid >= off) ? ssum[tid - off] : 0;
        __syncthreads();
        ssum[tid] += x;
        __syncthreads();
    }
    int texcl = ssum[tid] - s;
    int total = ssum[255];
    if (tid == 0) {
        if (t == 0) {
            g_tilest[0] = (2u << 30) | (unsigned)total;
            s_run = 0;
        } else {
            g_tilest[t] = (1u << 30) | (unsigned)total;
            int run = 0, p = t - 1;
            while (true) {
                unsigned w = g_tilest[p];
                unsigned f = w >> 30;
                if (f == 2u) { run += (int)(w & 0x3FFFFFFFu); break; }
                if (f == 1u) { run += (int)(w & 0x3FFFFFFFu); p--; }
            }
            g_tilest[t] = (2u << 30) | (unsigned)(run + total);
            s_run = run;
        }
    }
    __syncthreads();
    int ex = s_run + texcl;
    #pragma unroll
    for (int it = 0; it < 4; it++) {
        int idx = base + it;
        if (idx < Nn) {
            g_rowptr[idx] = ex;
            int dd = d[it];
            g_dinv[idx] = (dd > 0) ? 1.0f / (float)dd : 0.0f;
            ex += dd;
        }
    }
}

// CSR fill (atomic-free) + embedding gather ride-along
__global__ void k_fill_gather(const int* __restrict__ src, const int* __restrict__ dst,
                              const int* __restrict__ node_ids,
                              const float4* __restrict__ emb) {
    int i = blockIdx.x * blockDim.x + threadIdx.x;
    if (i < Ee) {
        int d = dst[i];
        g_csr[g_rowptr[d] + g_rank[i]] = src[i];
    }
    if (i < Nn * 4) {
        int n = i >> 2, c = i & 3;
        float4 v0 = emb[node_ids[n] * 8 + c * 2 + 0];
        float4 v1 = emb[node_ids[n] * 8 + c * 2 + 1];
        uint4 o;
        o.x = ph2(v0.x, v0.y); o.y = ph2(v0.z, v0.w);
        o.z = ph2(v1.x, v1.y); o.w = ph2(v1.z, v1.w);
        g_h0h[n * 4 + c] = o;
    }
}

// ---------------- aggregation ----------------

__global__ void k_agg1() {
    int t = blockIdx.x * blockDim.x + threadIdx.x;
    if (t >= Nn * 4) return;
    int n = t >> 2, c = t & 3;
    int beg = g_rowptr[n], cnt = g_deg[n];
    float a0=0.f,a1=0.f,a2=0.f,a3=0.f,a4=0.f,a5=0.f,a6=0.f,a7=0.f;
    for (int i = 0; i < cnt; i += 8) {
        int  idx[8];
        float m[8];
        #pragma unroll
        for (int j = 0; j < 8; j++) {
            int ii = i + j;
            int id = (ii < cnt) ? ii : cnt - 1;
            idx[j] = __ldg(&g_csr[beg + id]);
            m[j]   = (ii < cnt) ? 1.0f : 0.0f;
        }
        uint4 q0 = g_h0h[idx[0]*4+c], q1 = g_h0h[idx[1]*4+c];
        uint4 q2 = g_h0h[idx[2]*4+c], q3 = g_h0h[idx[3]*4+c];
        uint4 q4 = g_h0h[idx[4]*4+c], q5 = g_h0h[idx[5]*4+c];
        uint4 q6 = g_h0h[idx[6]*4+c], q7 = g_h0h[idx[7]*4+c];
        ACCM(q0, m[0]) ACCM(q1, m[1]) ACCM(q2, m[2]) ACCM(q3, m[3])
        ACCM(q4, m[4]) ACCM(q5, m[5]) ACCM(q6, m[6]) ACCM(q7, m[7])
    }
    float dinv = g_dinv[n];
    uint4 o;
    o.x = ph2(a0*dinv, a1*dinv); o.y = ph2(a2*dinv, a3*dinv);
    o.z = ph2(a4*dinv, a5*dinv); o.w = ph2(a6*dinv, a7*dinv);
    g_ag1h[n*4 + c] = o;
}

__global__ void k_agg2() {
    int t = blockIdx.x * blockDim.x + threadIdx.x;
    if (t >= Nn * 8) return;
    int n = t >> 3, c = t & 7;
    int beg = g_rowptr[n], cnt = g_deg[n];
    float a0=0.f,a1=0.f,a2=0.f,a3=0.f,a4=0.f,a5=0.f,a6=0.f,a7=0.f;
    for (int i = 0; i < cnt; i += 8) {
        int  idx[8];
        float m[8];
        #pragma unroll
        for (int j = 0; j < 8; j++) {
            int ii = i + j;
            int id = (ii < cnt) ? ii : cnt - 1;
            idx[j] = __ldg(&g_csr[beg + id]);
            m[j]   = (ii < cnt) ? 1.0f : 0.0f;
        }
        uint4 q0 = g_h1h[idx[0]*8+c], q1 = g_h1h[idx[1]*8+c];
        uint4 q2 = g_h1h[idx[2]*8+c], q3 = g_h1h[idx[3]*8+c];
        uint4 q4 = g_h1h[idx[4]*8+c], q5 = g_h1h[idx[5]*8+c];
        uint4 q6 = g_h1h[idx[6]*8+c], q7 = g_h1h[idx[7]*8+c];
        ACCM(q0, m[0]) ACCM(q1, m[1]) ACCM(q2, m[2]) ACCM(q3, m[3])
        ACCM(q4, m[4]) ACCM(q5, m[5]) ACCM(q6, m[6]) ACCM(q7, m[7])
    }
    float dinv = g_dinv[n];
    uint4 o;
    o.x = ph2(a0*dinv, a1*dinv); o.y = ph2(a2*dinv, a3*dinv);
    o.z = ph2(a4*dinv, a5*dinv); o.w = ph2(a6*dinv, a7*dinv);
    g_ag2h[n*8 + c] = o;
}

// ---------------- dense updates ----------------

__global__ void __launch_bounds__(256)
k_update1(const float* __restrict__ Wse, const float* __restrict__ Wne,
          const float* __restrict__ b) {
    __shared__ float sW[2 * EMB * HID];   // 16 KB
    __shared__ float sb[HID];
    int tid = threadIdx.x;
    for (int i = tid; i < EMB * HID; i += 256) { sW[i] = Wse[i]; sW[EMB*HID + i] = Wne[i]; }
    if (tid < HID) sb[tid] = b[tid];
    __syncthreads();

    int t = blockIdx.x * 256 + tid;
    if (t >= Nn / 2) return;
    int n0 = t * 2, n1 = n0 + 1;

    #pragma unroll 1
    for (int q = 0; q < 4; q++) {
        u64 acc0[8], acc1[8];
        #pragma unroll
        for (int j2 = 0; j2 < 8; j2++) {
            u64 bi = pack2(sb[q*16 + 2*j2], sb[q*16 + 2*j2 + 1]);
            acc0[j2] = bi; acc1[j2] = bi;
        }
        #pragma unroll 1
        for (int kk = 0; kk < 4; kk++) {
            uint4 qh0 = g_h0h[n0*4 + kk], qa0 = g_ag1h[n0*4 + kk];
            uint4 qh1 = g_h0h[n1*4 + kk], qa1 = g_ag1h[n1*4 + kk];
            #pragma unroll
            for (int ch = 0; ch < 8; ch++) {
                int k = kk*8 + ch;
                const ulonglong2* ws = (const ulonglong2*)&sW[k * HID + q*16];
                const ulonglong2* wn = (const ulonglong2*)&sW[(EMB + k) * HID + q*16];
                float h0 = hget(qh0, ch), a0f = hget(qa0, ch);
                float h1 = hget(qh1, ch), a1f = hget(qa1, ch);
                u64 bh0 = pack2(h0, h0), ba0 = pack2(a0f, a0f);
                u64 bh1 = pack2(h1, h1), ba1 = pack2(a1f, a1f);
                #pragma unroll
                for (int j4 = 0; j4 < 4; j4++) {
                    ulonglong2 w = ws[j4], v = wn[j4];
                    fma2(acc0[j4*2+0], bh0, w.x); fma2(acc0[j4*2+1], bh0, w.y);
                    fma2(acc1[j4*2+0], bh1, w.x); fma2(acc1[j4*2+1], bh1, w.y);
                    fma2(acc0[j4*2+0], ba0, v.x); fma2(acc0[j4*2+1], ba0, v.y);
                    fma2(acc1[j4*2+0], ba1, v.x); fma2(acc1[j4*2+1], ba1, v.y);
                }
            }
        }
        #pragma unroll
        for (int half = 0; half < 2; half++) {
            float x0,x1,x2,x3,x4,x5,x6,x7;
            unpack2(x0,x1, acc0[half*4+0]); unpack2(x2,x3, acc0[half*4+1]);
            unpack2(x4,x5, acc0[half*4+2]); unpack2(x6,x7, acc0[half*4+3]);
            uint4 o;
            o.x = ph2(fmaxf(x0,0.f), fmaxf(x1,0.f));
            o.y = ph2(fmaxf(x2,0.f), fmaxf(x3,0.f));
            o.z = ph2(fmaxf(x4,0.f), fmaxf(x5,0.f));
            o.w = ph2(fmaxf(x6,0.f), fmaxf(x7,0.f));
            g_h1h[n0*8 + q*2 + half] = o;
            unpack2(x0,x1, acc1[half*4+0]); unpack2(x2,x3, acc1[half*4+1]);
            unpack2(x4,x5, acc1[half*4+2]); unpack2(x6,x7, acc1[half*4+3]);
            o.x = ph2(fmaxf(x0,0.f), fmaxf(x1,0.f));
            o.y = ph2(fmaxf(x2,0.f), fmaxf(x3,0.f));
            o.z = ph2(fmaxf(x4,0.f), fmaxf(x5,0.f));
            o.w = ph2(fmaxf(x6,0.f), fmaxf(x7,0.f));
            g_h1h[n1*8 + q*2 + half] = o;
        }
    }
}

__global__ void __launch_bounds__(256)
k_update2(const float* __restrict__ Wse, const float* __restrict__ Wne,
          const float* __restrict__ b, const int* __restrict__ graph_ids) {
    __shared__ float sW[2 * HID * HID];   // 32 KB
    __shared__ float sb[HID];
    int tid = threadIdx.x;
    for (int i = tid; i < HID * HID; i += 256) { sW[i] = Wse[i]; sW[HID*HID + i] = Wne[i]; }
    if (tid < HID) sb[tid] = b[tid];
    __syncthreads();

    int t = blockIdx.x * 256 + tid;
    if (t >= Nn / 2) return;
    int n0 = t * 2, n1 = n0 + 1;
    int g0 = graph_ids[n0], g1 = graph_ids[n1];
    float4* hg0 = (float4*)&g_hg[g0 * HID];
    float4* hg1 = (float4*)&g_hg[g1 * HID];

    #pragma unroll 1
    for (int q = 0; q < 4; q++) {
        u64 acc0[8], acc1[8];
        #pragma unroll
        for (int j2 = 0; j2 < 8; j2++) {
            u64 bi = pack2(sb[q*16 + 2*j2], sb[q*16 + 2*j2 + 1]);
            acc0[j2] = bi; acc1[j2] = bi;
        }
        #pragma unroll 1
        for (int kk = 0; kk < 8; kk++) {
            uint4 qh0 = g_h1h[n0*8 + kk], qa0 = g_ag2h[n0*8 + kk];
            uint4 qh1 = g_h1h[n1*8 + kk], qa1 = g_ag2h[n1*8 + kk];
            #pragma unroll
            for (int ch = 0; ch < 8; ch++) {
                int k = kk*8 + ch;
                const ulonglong2* ws = (const ulonglong2*)&sW[k * HID + q*16];
                const ulonglong2* wn = (const ulonglong2*)&sW[(HID + k) * HID + q*16];
                float h0 = hget(qh0, ch), a0f = hget(qa0, ch);
                float h1 = hget(qh1, ch), a1f = hget(qa1, ch);
                u64 bh0 = pack2(h0, h0), ba0 = pack2(a0f, a0f);
                u64 bh1 = pack2(h1, h1), ba1 = pack2(a1f, a1f);
                #pragma unroll
                for (int j4 = 0; j4 < 4; j4++) {
                    ulonglong2 w = ws[j4], v = wn[j4];
                    fma2(acc0[j4*2+0], bh0, w.x); fma2(acc0[j4*2+1], bh0, w.y);
                    fma2(acc1[j4*2+0], bh1, w.x); fma2(acc1[j4*2+1], bh1, w.y);
                    fma2(acc0[j4*2+0], ba0, v.x); fma2(acc0[j4*2+1], ba0, v.y);
                    fma2(acc1[j4*2+0], ba1, v.x); fma2(acc1[j4*2+1], ba1, v.y);
                }
            }
        }
        #pragma unroll
        for (int j4 = 0; j4 < 4; j4++) {
            float x0,x1,x2,x3;
            unpack2(x0, x1, acc0[j4*2+0]);
            unpack2(x2, x3, acc0[j4*2+1]);
            red4(&hg0[q*4 + j4], make_float4(fmaxf(x0,0.f), fmaxf(x1,0.f),
                                             fmaxf(x2,0.f), fmaxf(x3,0.f)));
            unpack2(x0, x1, acc1[j4*2+0]);
            unpack2(x2, x3, acc1[j4*2+1]);
            red4(&hg1[q*4 + j4], make_float4(fmaxf(x0,0.f), fmaxf(x1,0.f),
                                             fmaxf(x2,0.f), fmaxf(x3,0.f)));
        }
    }
}

// scorer + state reset for next call.
// Blocks 0..1 (512 threads) run the scorer; every thread reads its own hg/cnt
// slice and zeroes it afterwards (same-thread, no hazard). All blocks help
// zero g_deg / g_tilest / g_ticket (not read here).
__global__ void __launch_bounds__(256)
k_final_zero(const float* __restrict__ Ws1, const float* __restrict__ bs1,
             const float* __restrict__ Ws2, const float* __restrict__ bs2,
             float* __restrict__ out) {
    __shared__ float sW[HID * HID];
    int tid = threadIdx.x;
    int gid = blockIdx.x * 256 + tid;
    int gstr = gridDim.x * 256;

    if (blockIdx.x < 2) {
        for (int i = tid; i < HID * HID; i += 256) sW[i] = Ws1[i];
        __syncthreads();
        int g = gid;
        if (g < Bb) {
            float cv = g_cnt[g];
            float inv = 1.0f / fmaxf(cv, 1.0f);
            float hv[HID];
            #pragma unroll
            for (int k = 0; k < HID; k++) hv[k] = g_hg[g * HID + k] * inv;
            float s = bs2[0];
            #pragma unroll 1
            for (int j = 0; j < HID; j++) {
                float t = bs1[j];
                #pragma unroll
                for (int k = 0; k < HID; k++) t += hv[k] * sW[k * HID + j];
                s += fmaxf(t, 0.f) * Ws2[j];
            }
            out[g] = s;
            // reset this graph's accumulators for the next call
            #pragma unroll
            for (int k = 0; k < HID; k++) g_hg[g * HID + k] = 0.f;
            g_cnt[g] = 0.f;
        }
    }
    // all blocks: zero degree histogram + scan state for next call
    for (int j = gid; j < Nn; j += gstr) g_deg[j] = 0;
    for (int j = gid; j < NT; j += gstr) g_tilest[j] = 0u;
    if (gid == 0) g_ticket = 0;
}

// ---------------- launcher ----------------
extern "C" void kernel_launch(void* const* d_in, const int* in_sizes, int n_in,
                              void* d_out, int out_size) {
    const int*    node_ids  = (const int*)   d_in[0];
    const int*    src       = (const int*)   d_in[1];
    const int*    dst       = (const int*)   d_in[2];
    const int*    graph_ids = (const int*)   d_in[3];
    const float4* emb       = (const float4*)d_in[4];
    const float*  W_self1   = (const float*) d_in[5];
    const float*  W_neigh1  = (const float*) d_in[6];
    const float*  b1        = (const float*) d_in[7];
    const float*  W_self2   = (const float*) d_in[8];
    const float*  W_neigh2  = (const float*) d_in[9];
    const float*  b2        = (const float*) d_in[10];
    const float*  Ws1       = (const float*) d_in[11];
    const float*  bs1       = (const float*) d_in[12];
    const float*  Ws2       = (const float*) d_in[13];
    const float*  bs2       = (const float*) d_in[14];
    float* out = (float*)d_out;

    k_deg        <<<(Ee + 255) / 256, 256>>>(dst, graph_ids);           // 0
    k_scan       <<<NT, 256>>>();                                       // 1
    k_fill_gather<<<(Ee + 255) / 256, 256>>>(src, dst, node_ids, emb);  // 2
    k_agg1       <<<(Nn * 4 + 255) / 256, 256>>>();                     // 3 <- profiled
    k_update1    <<<(Nn/2 + 255) / 256, 256>>>(W_self1, W_neigh1, b1);  // 4
    k_agg2       <<<(Nn * 8 + 255) / 256, 256>>>();                     // 5
    k_update2    <<<(Nn/2 + 255) / 256, 256>>>(W_self2, W_neigh2, b2, graph_ids); // 6
    k_final_zero <<<128, 256>>>(Ws1, bs1, Ws2, bs2, out);               // 7
}

// round 10
// speedup vs baseline: 1.0565x; 1.0565x over previous
#include <cuda_runtime.h>
#include <cuda_fp16.h>

typedef unsigned long long u64;

#define Nn   200000
#define Ee   3200000
#define Bb   512
#define EMB  32
#define HID  64
#define TILE 1024
#define NT   ((Nn + TILE - 1) / TILE)   // 196 scan tiles

// ---------------- scratch (device globals) ----------------
__device__ uint4 g_h0h [Nn * 4];          // 12.8 MB fp16 h0
__device__ uint4 g_ag1h[Nn * 4];          // 12.8 MB fp16 agg1
__device__ uint4 g_h1h [Nn * 8];          // 25.6 MB fp16 h1
__device__ uint4 g_ag2h[Nn * 8];          // 25.6 MB fp16 agg2
__device__ int   g_csr [Ee];              // 12.8 MB
__device__ int   g_rank[Ee];              // 12.8 MB edge rank within dst
__device__ int   g_rowptr[Nn];
__device__ int   g_deg [Nn];
__device__ float g_dinv[Nn];
__device__ float g_hg  [Bb * HID];
__device__ float g_cnt [Bb];
__device__ volatile unsigned g_tilest[NT];
__device__ int   g_ticket;

// ---------------- helpers ----------------
__device__ __forceinline__ void red4(float4* p, float4 v) {
    asm volatile("red.global.add.v4.f32 [%0], {%1,%2,%3,%4};"
                 :: "l"(p), "f"(v.x), "f"(v.y), "f"(v.z), "f"(v.w) : "memory");
}
__device__ __forceinline__ u64 pack2(float x, float y) {
    u64 r; asm("mov.b64 %0, {%1, %2};" : "=l"(r) : "f"(x), "f"(y)); return r;
}
__device__ __forceinline__ void fma2(u64& d, u64 a, u64 b) {
    asm("fma.rn.f32x2 %0, %1, %2, %0;" : "+l"(d) : "l"(a), "l"(b));
}
__device__ __forceinline__ void unpack2(float& x, float& y, u64 v) {
    asm("mov.b64 {%0, %1}, %2;" : "=f"(x), "=f"(y) : "l"(v));
}
__device__ __forceinline__ unsigned ph2(float a, float b) {
    __half2 h = __floats2half2_rn(a, b); return *(unsigned*)&h;
}
__device__ __forceinline__ float hget(const uint4& q, int ch) {
    unsigned w = (ch < 2) ? q.x : (ch < 4) ? q.y : (ch < 6) ? q.z : q.w;
    __half2 h = *(__half2*)&w;
    return (ch & 1) ? __high2float(h) : __low2float(h);
}
#define H2C(q, k) (*((const __half2*)&(q) + (k)))
// fp32 accumulate of a single uint4 (tail path)
#define ACCQ(q) { \
    float2 f0 = __half22float2(H2C(q,0)); \
    float2 f1 = __half22float2(H2C(q,1)); \
    float2 f2 = __half22float2(H2C(q,2)); \
    float2 f3 = __half22float2(H2C(q,3)); \
    a0+=f0.x; a1+=f0.y; a2+=f1.x; a3+=f1.y; \
    a4+=f2.x; a5+=f2.y; a6+=f3.x; a7+=f3.y; }
// pairwise fp16 sum of 4 uint4s, then fp32 accumulate (12 HADD2 + 8 cvt + 8 add)
#define ACC4(q0, q1, q2, q3) { \
    __half2 s0 = __hadd2(__hadd2(H2C(q0,0), H2C(q1,0)), __hadd2(H2C(q2,0), H2C(q3,0))); \
    __half2 s1 = __hadd2(__hadd2(H2C(q0,1), H2C(q1,1)), __hadd2(H2C(q2,1), H2C(q3,1))); \
    __half2 s2 = __hadd2(__hadd2(H2C(q0,2), H2C(q1,2)), __hadd2(H2C(q2,2), H2C(q3,2))); \
    __half2 s3 = __hadd2(__hadd2(H2C(q0,3), H2C(q1,3)), __hadd2(H2C(q2,3), H2C(q3,3))); \
    float2 f0 = __half22float2(s0); float2 f1 = __half22float2(s1); \
    float2 f2 = __half22float2(s2); float2 f3 = __half22float2(s3); \
    a0+=f0.x; a1+=f0.y; a2+=f1.x; a3+=f1.y; \
    a4+=f2.x; a5+=f2.y; a6+=f3.x; a7+=f3.y; }

// ---------------- setup kernels ----------------

__global__ void k_zero() {
    int i = blockIdx.x * blockDim.x + threadIdx.x;
    int stride = gridDim.x * blockDim.x;
    for (int j = i; j < Nn;       j += stride) g_deg[j] = 0;
    for (int j = i; j < Bb * HID; j += stride) g_hg[j]  = 0.f;
    for (int j = i; j < NT;       j += stride) g_tilest[j] = 0u;
    if (i < Bb) g_cnt[i] = 0.f;
    if (i == 0) g_ticket = 0;
}

// degree histogram (atomic return = edge rank) + graph-size histogram
__global__ void k_deg(const int* __restrict__ dst,
                      const int* __restrict__ graph_ids) {
    int i = blockIdx.x * blockDim.x + threadIdx.x;
    if (i < Ee) g_rank[i] = atomicAdd(&g_deg[dst[i]], 1);
    if (i < Nn) atomicAdd(&g_cnt[graph_ids[i]], 1.0f);
}

// single-pass decoupled-lookback exclusive scan
__global__ void __launch_bounds__(256) k_scan() {
    __shared__ int s_ticket, s_run;
    __shared__ int ssum[256];
    int tid = threadIdx.x;
    if (tid == 0) s_ticket = atomicAdd(&g_ticket, 1);
    __syncthreads();
    int t = s_ticket;
    int base = t * TILE + tid * 4;
    int d[4]; int s = 0;
    #pragma unroll
    for (int it = 0; it < 4; it++) {
        int idx = base + it;
        d[it] = (idx < Nn) ? g_deg[idx] : 0;
        s += d[it];
    }
    ssum[tid] = s; __syncthreads();
    #pragma unroll
    for (int off = 1; off < 256; off <<= 1) {
        int x = (tid >= off) ? ssum[tid - off] : 0;
        __syncthreads();
        ssum[tid] += x;
        __syncthreads();
    }
    int texcl = ssum[tid] - s;
    int total = ssum[255];
    if (tid == 0) {
        if (t == 0) {
            g_tilest[0] = (2u << 30) | (unsigned)total;
            s_run = 0;
        } else {
            g_tilest[t] = (1u << 30) | (unsigned)total;
            int run = 0, p = t - 1;
            while (true) {
                unsigned w = g_tilest[p];
                unsigned f = w >> 30;
                if (f == 2u) { run += (int)(w & 0x3FFFFFFFu); break; }
                if (f == 1u) { run += (int)(w & 0x3FFFFFFFu); p--; }
            }
            g_tilest[t] = (2u << 30) | (unsigned)(run + total);
            s_run = run;
        }
    }
    __syncthreads();
    int ex = s_run + texcl;
    #pragma unroll
    for (int it = 0; it < 4; it++) {
        int idx = base + it;
        if (idx < Nn) {
            g_rowptr[idx] = ex;
            int dd = d[it];
            g_dinv[idx] = (dd > 0) ? 1.0f / (float)dd : 0.0f;
            ex += dd;
        }
    }
}

// CSR fill (atomic-free) + embedding gather ride-along
__global__ void k_fill_gather(const int* __restrict__ src, const int* __restrict__ dst,
                              const int* __restrict__ node_ids,
                              const float4* __restrict__ emb) {
    int i = blockIdx.x * blockDim.x + threadIdx.x;
    if (i < Ee) {
        int d = dst[i];
        g_csr[g_rowptr[d] + g_rank[i]] = src[i];
    }
    if (i < Nn * 4) {
        int n = i >> 2, c = i & 3;
        float4 v0 = emb[node_ids[n] * 8 + c * 2 + 0];
        float4 v1 = emb[node_ids[n] * 8 + c * 2 + 1];
        uint4 o;
        o.x = ph2(v0.x, v0.y); o.y = ph2(v0.z, v0.w);
        o.z = ph2(v1.x, v1.y); o.w = ph2(v1.z, v1.w);
        g_h0h[n * 4 + c] = o;
    }
}

// ---------------- aggregation: pairwise fp16 sums, fp32 outer accumulate --------

__global__ void k_agg1() {
    int t = blockIdx.x * blockDim.x + threadIdx.x;
    if (t >= Nn * 4) return;
    int n = t >> 2, c = t & 3;
    int beg = g_rowptr[n], cnt = g_deg[n];
    float a0=0.f,a1=0.f,a2=0.f,a3=0.f,a4=0.f,a5=0.f,a6=0.f,a7=0.f;
    int i = 0;
    for (; i + 7 < cnt; i += 8) {
        int s0 = __ldg(&g_csr[beg+i+0]), s1 = __ldg(&g_csr[beg+i+1]);
        int s2 = __ldg(&g_csr[beg+i+2]), s3 = __ldg(&g_csr[beg+i+3]);
        int s4 = __ldg(&g_csr[beg+i+4]), s5 = __ldg(&g_csr[beg+i+5]);
        int s6 = __ldg(&g_csr[beg+i+6]), s7 = __ldg(&g_csr[beg+i+7]);
        uint4 q0 = g_h0h[s0*4+c], q1 = g_h0h[s1*4+c];
        uint4 q2 = g_h0h[s2*4+c], q3 = g_h0h[s3*4+c];
        uint4 q4 = g_h0h[s4*4+c], q5 = g_h0h[s5*4+c];
        uint4 q6 = g_h0h[s6*4+c], q7 = g_h0h[s7*4+c];
        ACC4(q0, q1, q2, q3)
        ACC4(q4, q5, q6, q7)
    }
    for (; i + 3 < cnt; i += 4) {
        int s0 = __ldg(&g_csr[beg+i+0]), s1 = __ldg(&g_csr[beg+i+1]);
        int s2 = __ldg(&g_csr[beg+i+2]), s3 = __ldg(&g_csr[beg+i+3]);
        uint4 q0 = g_h0h[s0*4+c], q1 = g_h0h[s1*4+c];
        uint4 q2 = g_h0h[s2*4+c], q3 = g_h0h[s3*4+c];
        ACC4(q0, q1, q2, q3)
    }
    for (; i < cnt; i++) {
        int s = __ldg(&g_csr[beg+i]);
        uint4 q = g_h0h[s*4+c];
        ACCQ(q)
    }
    float dinv = g_dinv[n];
    uint4 o;
    o.x = ph2(a0*dinv, a1*dinv); o.y = ph2(a2*dinv, a3*dinv);
    o.z = ph2(a4*dinv, a5*dinv); o.w = ph2(a6*dinv, a7*dinv);
    g_ag1h[n*4 + c] = o;
}

__global__ void k_agg2() {
    int t = blockIdx.x * blockDim.x + threadIdx.x;
    if (t >= Nn * 8) return;
    int n = t >> 3, c = t & 7;
    int beg = g_rowptr[n], cnt = g_deg[n];
    float a0=0.f,a1=0.f,a2=0.f,a3=0.f,a4=0.f,a5=0.f,a6=0.f,a7=0.f;
    int i = 0;
    for (; i + 7 < cnt; i += 8) {
        int s0 = __ldg(&g_csr[beg+i+0]), s1 = __ldg(&g_csr[beg+i+1]);
        int s2 = __ldg(&g_csr[beg+i+2]), s3 = __ldg(&g_csr[beg+i+3]);
        int s4 = __ldg(&g_csr[beg+i+4]), s5 = __ldg(&g_csr[beg+i+5]);
        int s6 = __ldg(&g_csr[beg+i+6]), s7 = __ldg(&g_csr[beg+i+7]);
        uint4 q0 = g_h1h[s0*8+c], q1 = g_h1h[s1*8+c];
        uint4 q2 = g_h1h[s2*8+c], q3 = g_h1h[s3*8+c];
        uint4 q4 = g_h1h[s4*8+c], q5 = g_h1h[s5*8+c];
        uint4 q6 = g_h1h[s6*8+c], q7 = g_h1h[s7*8+c];
        ACC4(q0, q1, q2, q3)
        ACC4(q4, q5, q6, q7)
    }
    for (; i + 3 < cnt; i += 4) {
        int s0 = __ldg(&g_csr[beg+i+0]), s1 = __ldg(&g_csr[beg+i+1]);
        int s2 = __ldg(&g_csr[beg+i+2]), s3 = __ldg(&g_csr[beg+i+3]);
        uint4 q0 = g_h1h[s0*8+c], q1 = g_h1h[s1*8+c];
        uint4 q2 = g_h1h[s2*8+c], q3 = g_h1h[s3*8+c];
        ACC4(q0, q1, q2, q3)
    }
    for (; i < cnt; i++) {
        int s = __ldg(&g_csr[beg+i]);
        uint4 q = g_h1h[s*8+c];
        ACCQ(q)
    }
    float dinv = g_dinv[n];
    uint4 o;
    o.x = ph2(a0*dinv, a1*dinv); o.y = ph2(a2*dinv, a3*dinv);
    o.z = ph2(a4*dinv, a5*dinv); o.w = ph2(a6*dinv, a7*dinv);
    g_ag2h[n*8 + c] = o;
}

// ---------------- dense updates (unchanged from R8) ----------------

__global__ void __launch_bounds__(256)
k_update1(const float* __restrict__ Wse, const float* __restrict__ Wne,
          const float* __restrict__ b) {
    __shared__ float sW[2 * EMB * HID];   // 16 KB
    __shared__ float sb[HID];
    int tid = threadIdx.x;
    for (int i = tid; i < EMB * HID; i += 256) { sW[i] = Wse[i]; sW[EMB*HID + i] = Wne[i]; }
    if (tid < HID) sb[tid] = b[tid];
    __syncthreads();

    int t = blockIdx.x * 256 + tid;
    if (t >= Nn / 2) return;
    int n0 = t * 2, n1 = n0 + 1;

    #pragma unroll 1
    for (int q = 0; q < 4; q++) {
        u64 acc0[8], acc1[8];
        #pragma unroll
        for (int j2 = 0; j2 < 8; j2++) {
            u64 bi = pack2(sb[q*16 + 2*j2], sb[q*16 + 2*j2 + 1]);
            acc0[j2] = bi; acc1[j2] = bi;
        }
        #pragma unroll 1
        for (int kk = 0; kk < 4; kk++) {
            uint4 qh0 = g_h0h[n0*4 + kk], qa0 = g_ag1h[n0*4 + kk];
            uint4 qh1 = g_h0h[n1*4 + kk], qa1 = g_ag1h[n1*4 + kk];
            #pragma unroll
            for (int ch = 0; ch < 8; ch++) {
                int k = kk*8 + ch;
                const ulonglong2* ws = (const ulonglong2*)&sW[k * HID + q*16];
                const ulonglong2* wn = (const ulonglong2*)&sW[(EMB + k) * HID + q*16];
                float h0 = hget(qh0, ch), a0f = hget(qa0, ch);
                float h1 = hget(qh1, ch), a1f = hget(qa1, ch);
                u64 bh0 = pack2(h0, h0), ba0 = pack2(a0f, a0f);
                u64 bh1 = pack2(h1, h1), ba1 = pack2(a1f, a1f);
                #pragma unroll
                for (int j4 = 0; j4 < 4; j4++) {
                    ulonglong2 w = ws[j4], v = wn[j4];
                    fma2(acc0[j4*2+0], bh0, w.x); fma2(acc0[j4*2+1], bh0, w.y);
                    fma2(acc1[j4*2+0], bh1, w.x); fma2(acc1[j4*2+1], bh1, w.y);
                    fma2(acc0[j4*2+0], ba0, v.x); fma2(acc0[j4*2+1], ba0, v.y);
                    fma2(acc1[j4*2+0], ba1, v.x); fma2(acc1[j4*2+1], ba1, v.y);
                }
            }
        }
        #pragma unroll
        for (int half = 0; half < 2; half++) {
            float x0,x1,x2,x3,x4,x5,x6,x7;
            unpack2(x0,x1, acc0[half*4+0]); unpack2(x2,x3, acc0[half*4+1]);
            unpack2(x4,x5, acc0[half*4+2]); unpack2(x6,x7, acc0[half*4+3]);
            uint4 o;
            o.x = ph2(fmaxf(x0,0.f), fmaxf(x1,0.f));
            o.y = ph2(fmaxf(x2,0.f), fmaxf(x3,0.f));
            o.z = ph2(fmaxf(x4,0.f), fmaxf(x5,0.f));
            o.w = ph2(fmaxf(x6,0.f), fmaxf(x7,0.f));
            g_h1h[n0*8 + q*2 + half] = o;
            unpack2(x0,x1, acc1[half*4+0]); unpack2(x2,x3, acc1[half*4+1]);
            unpack2(x4,x5, acc1[half*4+2]); unpack2(x6,x7, acc1[half*4+3]);
            o.x = ph2(fmaxf(x0,0.f), fmaxf(x1,0.f));
            o.y = ph2(fmaxf(x2,0.f), fmaxf(x3,0.f));
            o.z = ph2(fmaxf(x4,0.f), fmaxf(x5,0.f));
            o.w = ph2(fmaxf(x6,0.f), fmaxf(x7,0.f));
            g_h1h[n1*8 + q*2 + half] = o;
        }
    }
}

__global__ void __launch_bounds__(256)
k_update2(const float* __restrict__ Wse, const float* __restrict__ Wne,
          const float* __restrict__ b, const int* __restrict__ graph_ids) {
    __shared__ float sW[2 * HID * HID];   // 32 KB
    __shared__ float sb[HID];
    int tid = threadIdx.x;
    for (int i = tid; i < HID * HID; i += 256) { sW[i] = Wse[i]; sW[HID*HID + i] = Wne[i]; }
    if (tid < HID) sb[tid] = b[tid];
    __syncthreads();

    int t = blockIdx.x * 256 + tid;
    if (t >= Nn / 2) return;
    int n0 = t * 2, n1 = n0 + 1;
    int g0 = graph_ids[n0], g1 = graph_ids[n1];
    float4* hg0 = (float4*)&g_hg[g0 * HID];
    float4* hg1 = (float4*)&g_hg[g1 * HID];

    #pragma unroll 1
    for (int q = 0; q < 4; q++) {
        u64 acc0[8], acc1[8];
        #pragma unroll
        for (int j2 = 0; j2 < 8; j2++) {
            u64 bi = pack2(sb[q*16 + 2*j2], sb[q*16 + 2*j2 + 1]);
            acc0[j2] = bi; acc1[j2] = bi;
        }
        #pragma unroll 1
        for (int kk = 0; kk < 8; kk++) {
            uint4 qh0 = g_h1h[n0*8 + kk], qa0 = g_ag2h[n0*8 + kk];
            uint4 qh1 = g_h1h[n1*8 + kk], qa1 = g_ag2h[n1*8 + kk];
            #pragma unroll
            for (int ch = 0; ch < 8; ch++) {
                int k = kk*8 + ch;
                const ulonglong2* ws = (const ulonglong2*)&sW[k * HID + q*16];
                const ulonglong2* wn = (const ulonglong2*)&sW[(HID + k) * HID + q*16];
                float h0 = hget(qh0, ch), a0f = hget(qa0, ch);
                float h1 = hget(qh1, ch), a1f = hget(qa1, ch);
                u64 bh0 = pack2(h0, h0), ba0 = pack2(a0f, a0f);
                u64 bh1 = pack2(h1, h1), ba1 = pack2(a1f, a1f);
                #pragma unroll
                for (int j4 = 0; j4 < 4; j4++) {
                    ulonglong2 w = ws[j4], v = wn[j4];
                    fma2(acc0[j4*2+0], bh0, w.x); fma2(acc0[j4*2+1], bh0, w.y);
                    fma2(acc1[j4*2+0], bh1, w.x); fma2(acc1[j4*2+1], bh1, w.y);
                    fma2(acc0[j4*2+0], ba0, v.x); fma2(acc0[j4*2+1], ba0, v.y);
                    fma2(acc1[j4*2+0], ba1, v.x); fma2(acc1[j4*2+1], ba1, v.y);
                }
            }
        }
        #pragma unroll
        for (int j4 = 0; j4 < 4; j4++) {
            float x0,x1,x2,x3;
            unpack2(x0, x1, acc0[j4*2+0]);
            unpack2(x2, x3, acc0[j4*2+1]);
            red4(&hg0[q*4 + j4], make_float4(fmaxf(x0,0.f), fmaxf(x1,0.f),
                                             fmaxf(x2,0.f), fmaxf(x3,0.f)));
            unpack2(x0, x1, acc1[j4*2+0]);
            unpack2(x2, x3, acc1[j4*2+1]);
            red4(&hg1[q*4 + j4], make_float4(fmaxf(x0,0.f), fmaxf(x1,0.f),
                                             fmaxf(x2,0.f), fmaxf(x3,0.f)));
        }
    }
}

// scorer
__global__ void k_final(const float* __restrict__ Ws1, const float* __restrict__ bs1,
                        const float* __restrict__ Ws2, const float* __restrict__ bs2,
                        float* __restrict__ out) {
    __shared__ float sW[HID * HID];
    int tid = threadIdx.x;
    for (int i = tid; i < HID * HID; i += 64) sW[i] = Ws1[i];
    __syncthreads();

    int g = blockIdx.x * 64 + tid;
    if (g >= Bb) return;

    float inv = 1.0f / fmaxf(g_cnt[g], 1.0f);
    float hv[HID];
    #pragma unroll
    for (int k = 0; k < HID; k++) hv[k] = g_hg[g * HID + k] * inv;

    float s = bs2[0];
    #pragma unroll 1
    for (int j = 0; j < HID; j++) {
        float t = bs1[j];
        #pragma unroll
        for (int k = 0; k < HID; k++) t += hv[k] * sW[k * HID + j];
        s += fmaxf(t, 0.f) * Ws2[j];
    }
    out[g] = s;
}

// ---------------- launcher ----------------
extern "C" void kernel_launch(void* const* d_in, const int* in_sizes, int n_in,
                              void* d_out, int out_size) {
    const int*    node_ids  = (const int*)   d_in[0];
    const int*    src       = (const int*)   d_in[1];
    const int*    dst       = (const int*)   d_in[2];
    const int*    graph_ids = (const int*)   d_in[3];
    const float4* emb       = (const float4*)d_in[4];
    const float*  W_self1   = (const float*) d_in[5];
    const float*  W_neigh1  = (const float*) d_in[6];
    const float*  b1        = (const float*) d_in[7];
    const float*  W_self2   = (const float*) d_in[8];
    const float*  W_neigh2  = (const float*) d_in[9];
    const float*  b2        = (const float*) d_in[10];
    const float*  Ws1       = (const float*) d_in[11];
    const float*  bs1       = (const float*) d_in[12];
    const float*  Ws2       = (const float*) d_in[13];
    const float*  bs2       = (const float*) d_in[14];
    float* out = (float*)d_out;

    k_zero       <<<512, 256>>>();                                      // 0
    k_deg        <<<(Ee + 255) / 256, 256>>>(dst, graph_ids);           // 1
    k_scan       <<<NT, 256>>>();                                       // 2
    k_fill_gather<<<(Ee + 255) / 256, 256>>>(src, dst, node_ids, emb);  // 3 <- profiled
    k_agg1       <<<(Nn * 4 + 255) / 256, 256>>>();                     // 4
    k_update1    <<<(Nn/2 + 255) / 256, 256>>>(W_self1, W_neigh1, b1);  // 5
    k_agg2       <<<(Nn * 8 + 255) / 256, 256>>>();                     // 6
    k_update2    <<<(Nn/2 + 255) / 256, 256>>>(W_self2, W_neigh2, b2, graph_ids); // 7
    k_final      <<<(Bb + 63) / 64, 64>>>(Ws1, bs1, Ws2, bs2, out);     // 8
}